// round 14
// baseline (speedup 1.0000x reference)
#include <cuda_runtime.h>
#include <cuda_fp16.h>
#include <cstdint>

#define Bb 16
#define Nn 2048
#define Hh 128

// ---------------- scratch ----------------
__device__ __half g_Ah[(size_t)Bb * Nn * Nn];      // adj fp16 + self loops, [b][j][i]
__device__ float  g_deg[Bb * Nn];
__device__ float  g_dis[Bb * Nn];
__device__ __half g_Xs[(size_t)Bb * Hh * Nn];      // [b][h][j]
__device__ __half g_h [(size_t)Bb * Hh * Nn];
__device__ __half g_w16[4 * Hh * Hh];              // W2^T, W3^T, A1low^T, A2^T (row-major MxK)
__device__ float  g_pool[Bb * Hh];                 // raw sums (x2048)
__device__ float  g_bias1[Bb * Hh];
__device__ float  g_scores[Bb * Nn];

// ---------------- helpers ----------------
__device__ __forceinline__ uint32_t smem_u32(const void* p) {
    uint32_t a;
    asm("{ .reg .u64 t; cvta.to.shared.u64 t, %1; cvt.u32.u64 %0, t; }" : "=r"(a) : "l"(p));
    return a;
}
__device__ __forceinline__ void cp16(uint32_t s, const void* g) {
    asm volatile("cp.async.cg.shared.global [%0], [%1], 16;" :: "r"(s), "l"(g));
}
#define CP_COMMIT() asm volatile("cp.async.commit_group;" ::: "memory")
#define CP_WAIT(n)  asm volatile("cp.async.wait_group %0;" :: "n"(n) : "memory")

__device__ __forceinline__ void ldsm4(uint32_t* r, uint32_t addr) {
    asm volatile("ldmatrix.sync.aligned.m8n8.x4.shared.b16 {%0,%1,%2,%3}, [%4];"
                 : "=r"(r[0]), "=r"(r[1]), "=r"(r[2]), "=r"(r[3]) : "r"(addr));
}
__device__ __forceinline__ void ldsm4t(uint32_t* r, uint32_t addr) {
    asm volatile("ldmatrix.sync.aligned.m8n8.x4.trans.shared.b16 {%0,%1,%2,%3}, [%4];"
                 : "=r"(r[0]), "=r"(r[1]), "=r"(r[2]), "=r"(r[3]) : "r"(addr));
}
__device__ __forceinline__ void mma16816(float* c, const uint32_t* a, uint32_t b0, uint32_t b1) {
    asm volatile("mma.sync.aligned.m16n8k16.row.col.f32.f16.f16.f32 "
                 "{%0,%1,%2,%3}, {%4,%5,%6,%7}, {%8,%9}, {%0,%1,%2,%3};"
                 : "+f"(c[0]), "+f"(c[1]), "+f"(c[2]), "+f"(c[3])
                 : "r"(a[0]), "r"(a[1]), "r"(a[2]), "r"(a[3]), "r"(b0), "r"(b1));
}

// ---------------- degree + fp16 conversion (int4-vectorized) ----------------
__global__ void k_deg_convert(const int* __restrict__ adj) {
    int b  = blockIdx.y;
    int j0 = blockIdx.x * 64;
    int tid = threadIdx.x;
    int c0 = tid * 8;
    float sum[8];
#pragma unroll
    for (int s = 0; s < 8; s++) sum[s] = 0.f;
    const int*  base  = adj  + ((size_t)b * Nn + j0) * Nn;
    __half*     obase = g_Ah + ((size_t)b * Nn + j0) * Nn;
    for (int r = 0; r < 64; r++) {
        int j = j0 + r;
        const int4* row = (const int4*)(base + (size_t)r * Nn + c0);
        int4 v0 = row[0], v1 = row[1];
        float a[8];
        a[0] = (v0.x != 0 || j == c0 + 0) ? 1.f : 0.f;
        a[1] = (v0.y != 0 || j == c0 + 1) ? 1.f : 0.f;
        a[2] = (v0.z != 0 || j == c0 + 2) ? 1.f : 0.f;
        a[3] = (v0.w != 0 || j == c0 + 3) ? 1.f : 0.f;
        a[4] = (v1.x != 0 || j == c0 + 4) ? 1.f : 0.f;
        a[5] = (v1.y != 0 || j == c0 + 5) ? 1.f : 0.f;
        a[6] = (v1.z != 0 || j == c0 + 6) ? 1.f : 0.f;
        a[7] = (v1.w != 0 || j == c0 + 7) ? 1.f : 0.f;
        __half2 hb[4];
#pragma unroll
        for (int e = 0; e < 4; e++) hb[e] = __floats2half2_rn(a[2 * e], a[2 * e + 1]);
        *(uint4*)(obase + (size_t)r * Nn + c0) = *(const uint4*)hb;
#pragma unroll
        for (int e = 0; e < 8; e++) sum[e] += a[e];
    }
#pragma unroll
    for (int e = 0; e < 8; e++) atomicAdd(&g_deg[b * Nn + c0 + e], sum[e]);
}

__global__ void k_dis() {
    int i = blockIdx.x * 256 + threadIdx.x;
    g_dis[i] = rsqrtf(g_deg[i]);
}

__global__ void k_convw(const float* __restrict__ W2, const float* __restrict__ W3,
                        const float* __restrict__ A1, const float* __restrict__ A2) {
    int i = blockIdx.x * 256 + threadIdx.x;
    int r = i >> 7, c = i & 127;
    int t = c * 128 + r;
    g_w16[i]               = __float2half(W2[t]);
    g_w16[Hh * Hh + i]     = __float2half(W3[t]);
    g_w16[2 * Hh * Hh + i] = __float2half(A1[t]);
    g_w16[3 * Hh * Hh + i] = __float2half(A2[t]);
}

__global__ void k_xs1(const float* __restrict__ f, const float* __restrict__ W1) {
    int b = blockIdx.y, j0 = blockIdx.x * 128;
    int tid = threadIdx.x;
    __shared__ float sf0[128], sf1[128], sd[128], sw[256];
    if (tid < 128) {
        int j = j0 + tid;
        sf0[tid] = f[((size_t)b * Nn + j) * 2];
        sf1[tid] = f[((size_t)b * Nn + j) * 2 + 1];
        sd[tid]  = g_dis[b * Nn + j];
    }
    sw[tid] = W1[tid];
    __syncthreads();
#pragma unroll
    for (int t = 0; t < 32; t++) {
        int idx = t * 256 + tid;
        int h = idx >> 6, jp = (idx & 63) << 1;
        float v0 = sd[jp]     * (sf0[jp]     * sw[h] + sf1[jp]     * sw[128 + h]);
        float v1 = sd[jp + 1] * (sf0[jp + 1] * sw[h] + sf1[jp + 1] * sw[128 + h]);
        *(__half2*)(g_Xs + ((size_t)b * Hh + h) * Nn + j0 + jp) = __floats2half2_rn(v0, v1);
    }
}

// ---------------- mma.sync GEMM ----------------
// 4 warps (2x2), warp tile 64x64, BK=64, 3-stage cp.async, register double-buffered
// fragments, ONE barrier per k-iter, 2 CTAs/SM.
#define BM 128
#define BN 128
#define BK 64
#define NT 128
#define LDA_S 72
#define LDB_S 136
#define LDC_S 136
#define A_ST (BM * LDA_S)
#define B_ST (BK * LDB_S)
#define STAGE_H (A_ST + B_ST)
#define GEMM_SMEM (3 * STAGE_H * 2)   // 107520 B -> 2 CTAs/SM

#define LDSM_GROUP(AF, BF, as, bs, kk)                                   \
    do {                                                                 \
        _Pragma("unroll")                                                \
        for (int _x = 0; _x < 4; _x++)                                   \
            ldsm4(AF[_x], (as) + (_x * 16 * LDA_S + (kk)) * 2);          \
        _Pragma("unroll")                                                \
        for (int _y = 0; _y < 4; _y++)                                   \
            ldsm4t(BF[_y], (bs) + ((kk) * LDB_S + _y * 16) * 2);         \
    } while (0)

#define MMA_GROUP(AF, BF)                                                \
    do {                                                                 \
        _Pragma("unroll")                                                \
        for (int _x = 0; _x < 4; _x++)                                   \
            _Pragma("unroll")                                            \
            for (int _t = 0; _t < 8; _t++)                               \
                mma16816(c[_x][_t], AF[_x],                              \
                         BF[_t >> 1][(_t & 1) * 2],                      \
                         BF[_t >> 1][(_t & 1) * 2 + 1]);                 \
    } while (0)

// outMode: 0 = store C fp16; 1 = store C + pool atomics; 2 = scores only;
//          3 = fused actor head: a1 = relu(A·h + brbias); a2 = relu(Wproj·a1 + rb2);
//              scores[n] = 10*(sum_m a2[m][n]*A3[m] + ab3)
__global__ void __launch_bounds__(NT, 2) k_gemm(
    const __half* __restrict__ gA, size_t sA, int lda,
    const __half* __restrict__ gB, size_t sB, int ldb,
    __half* __restrict__ gC, size_t sC, int K,
    const float* __restrict__ cscale, const float* __restrict__ rbias,
    const float* __restrict__ brbias, int doRelu, int outMode,
    const float* __restrict__ pA3, const float* __restrict__ pab3,
    const float* __restrict__ rb2, const __half* __restrict__ Wproj,
    float* __restrict__ poolOut, float* __restrict__ scoresOut)
{
    extern __shared__ char smem[];
    uint32_t sb32 = smem_u32(smem);
    int tid = threadIdx.x, warp = tid >> 5, lane = tid & 31;
    int wm = warp >> 1, wn = warp & 1;            // 2 x 2 warps; warp tile 64 x 64
    int b = blockIdx.y, n0 = blockIdx.x * BN;
    const __half* A  = gA + (size_t)b * sA;
    const __half* Bp = gB + (size_t)b * sB;

    __shared__ float sb1[128];
    if (outMode == 3) sb1[tid] = brbias[b * Hh + tid];

    float c[4][8][4];
#pragma unroll
    for (int x = 0; x < 4; x++)
#pragma unroll
        for (int t = 0; t < 8; t++)
#pragma unroll
            for (int e = 0; e < 4; e++) c[x][t][e] = 0.f;

    auto load_stage = [&](int st, int k0) {
        uint32_t as = sb32 + st * STAGE_H * 2;
        uint32_t bs = as + A_ST * 2;
#pragma unroll
        for (int t = 0; t < 8; t++) {
            int cc = tid + t * NT;
            int ar = cc >> 3, ak = (cc & 7) << 3;
            cp16(as + (ar * LDA_S + ak) * 2, A + (size_t)ar * lda + k0 + ak);
        }
#pragma unroll
        for (int t = 0; t < 8; t++) {
            int cc = tid + t * NT;
            int br = cc >> 4, bn = (cc & 15) << 3;
            cp16(bs + (br * LDB_S + bn) * 2, Bp + (size_t)(k0 + br) * ldb + n0 + bn);
        }
    };

    uint32_t a_off = ((wm * 64 + (lane & 15)) * LDA_S + ((lane >> 4) << 3)) * 2;
    uint32_t b_off = ((lane & 15) * LDB_S + wn * 64 + ((lane >> 4) << 3)) * 2;

    uint32_t af0[4][4], bf0[4][4], af1[4][4], bf1[4][4];

    int KI = K >> 6;
    if (outMode == 3) {
        // preload Wproj (A2^T, 128x128 row-major) into stage-2 A region
        uint32_t ws = sb32 + 2 * STAGE_H * 2;
#pragma unroll
        for (int t = 0; t < 16; t++) {
            int cc = tid + t * NT;
            int ar = cc >> 4, ak = (cc & 15) << 3;
            cp16(ws + (ar * LDA_S + ak) * 2, Wproj + ar * Hh + ak);
        }
        CP_COMMIT();
    }
    load_stage(0, 0); CP_COMMIT();
    load_stage(1, BK); CP_COMMIT();
    CP_WAIT(1);
    __syncthreads();
    {
        uint32_t as = sb32 + a_off;
        uint32_t bs = sb32 + A_ST * 2 + b_off;
        LDSM_GROUP(af0, bf0, as, bs, 0);
    }

    for (int i = 0; i < KI; i++) {
        uint32_t as = sb32 + (i % 3) * STAGE_H * 2 + a_off;
        uint32_t bs = sb32 + (i % 3) * STAGE_H * 2 + A_ST * 2 + b_off;
        LDSM_GROUP(af1, bf1, as, bs, 16);
        MMA_GROUP(af0, bf0);
        LDSM_GROUP(af0, bf0, as, bs, 32);
        MMA_GROUP(af1, bf1);
        LDSM_GROUP(af1, bf1, as, bs, 48);
        MMA_GROUP(af0, bf0);
        if (i + 2 < KI && outMode != 3) {
            load_stage((i + 2) % 3, (i + 2) * BK);
            CP_COMMIT();
            CP_WAIT(1);
        } else if (i < KI - 1) {
            CP_WAIT(0);
        }
        if (i < KI - 1) {
            __syncthreads();
            uint32_t as2 = sb32 + ((i + 1) % 3) * STAGE_H * 2 + a_off;
            uint32_t bs2 = sb32 + ((i + 1) % 3) * STAGE_H * 2 + A_ST * 2 + b_off;
            LDSM_GROUP(af0, bf0, as2, bs2, 0);
        }
        MMA_GROUP(af1, bf1);
    }
    __syncthreads();

    if (outMode == 3) {
        // a1 = relu(c + bias1) -> fp16 tile in slot0 (B layout: rows = feature, cols = node)
        __half* Hs = (__half*)smem;
        {
            int r = lane >> 2, cq = (lane & 3) * 2;
#pragma unroll
            for (int x = 0; x < 4; x++) {
                int m0 = wm * 64 + x * 16 + r;
                float bb0 = sb1[m0], bb1 = sb1[m0 + 8];
#pragma unroll
                for (int t = 0; t < 8; t++) {
                    int nb = wn * 64 + t * 8 + cq;
                    *(__half2*)(Hs + m0 * LDB_S + nb) =
                        __floats2half2_rn(fmaxf(c[x][t][0] + bb0, 0.f), fmaxf(c[x][t][1] + bb0, 0.f));
                    *(__half2*)(Hs + (m0 + 8) * LDB_S + nb) =
                        __floats2half2_rn(fmaxf(c[x][t][2] + bb1, 0.f), fmaxf(c[x][t][3] + bb1, 0.f));
                }
            }
        }
        __syncthreads();
        // second GEMM: a2 = A2^T (slot2 A region) * a1 (slot0), K=128
#pragma unroll
        for (int x = 0; x < 4; x++)
#pragma unroll
            for (int t = 0; t < 8; t++)
#pragma unroll
                for (int e = 0; e < 4; e++) c[x][t][e] = 0.f;
        uint32_t as2 = sb32 + 2 * STAGE_H * 2 + a_off;
        uint32_t bs2 = sb32 + b_off;
        LDSM_GROUP(af0, bf0, as2, bs2, 0);
#pragma unroll
        for (int kk = 0; kk < 128; kk += 32) {
            LDSM_GROUP(af1, bf1, as2, bs2, kk + 16);
            MMA_GROUP(af0, bf0);
            if (kk + 32 < 128) LDSM_GROUP(af0, bf0, as2, bs2, kk + 32);
            MMA_GROUP(af1, bf1);
        }
        __syncthreads();
    }

    // stage accumulators to fp32 smem
    float* Cs = (float*)smem;
    {
        int r = lane >> 2, cq = (lane & 3) * 2;
#pragma unroll
        for (int x = 0; x < 4; x++)
#pragma unroll
            for (int t = 0; t < 8; t++) {
                int base = (wm * 64 + x * 16 + r) * LDC_S + wn * 64 + t * 8 + cq;
                Cs[base]     = c[x][t][0];
                Cs[base + 1] = c[x][t][1];
                Cs[base + 8 * LDC_S]     = c[x][t][2];
                Cs[base + 8 * LDC_S + 1] = c[x][t][3];
            }
    }
    __syncthreads();

    const float* cs = cscale ? cscale + (size_t)b * Nn + n0 : nullptr;

    if (outMode >= 2) {
        __shared__ float sA3[128], sb2[128];
        const float* bp = (outMode == 2) ? rbias : rb2;
        sA3[tid] = pA3[tid]; sb2[tid] = bp[tid];
        __syncthreads();
        int n = tid;
        float accv = 0.f;
#pragma unroll 4
        for (int m = 0; m < 128; m++) {
            float v = fmaxf(Cs[m * LDC_S + n] + sb2[m], 0.f);
            accv += v * sA3[m];
        }
        scoresOut[(size_t)b * Nn + n0 + n] = 10.f * (accv + pab3[0]);
        return;
    }

    const float* bbp = brbias ? brbias + b * Hh : nullptr;
#pragma unroll
    for (int t = 0; t < 16; t++) {
        int cc = tid + t * NT;
        int m = cc >> 4, nc = (cc & 15) << 3;
        float rbv = 0.f;
        if (rbias) rbv += rbias[m];
        if (bbp)   rbv += bbp[m];
        __half2 hb[4];
#pragma unroll
        for (int e = 0; e < 8; e += 2) {
            float v0 = Cs[m * LDC_S + nc + e];
            float v1 = Cs[m * LDC_S + nc + e + 1];
            if (cs) { v0 *= cs[nc + e]; v1 *= cs[nc + e + 1]; }
            v0 += rbv; v1 += rbv;
            if (doRelu) { v0 = fmaxf(v0, 0.f); v1 = fmaxf(v1, 0.f); }
            hb[e >> 1] = __floats2half2_rn(v0, v1);
        }
        *(uint4*)(gC + (size_t)b * sC + (size_t)m * Nn + n0 + nc) = *(const uint4*)hb;
    }
    if (outMode == 1) {
        int m = tid;
        float rbv = rbias ? rbias[m] : 0.f;
        float part = 0.f;
#pragma unroll 4
        for (int n = 0; n < 128; n++) {
            float v = Cs[m * LDC_S + n];
            if (cs) v *= cs[n];
            part += fmaxf(v + rbv, 0.f);
        }
        atomicAdd(&poolOut[b * Hh + m], part);
    }
}

// ---------------- bias1, final ----------------
__global__ void k_bias1(const float* __restrict__ A1, const float* __restrict__ ab1,
                        const float* __restrict__ ms) {
    int b = blockIdx.x, h = threadIdx.x;
    const float inv = 1.f / 2048.f;
    float acc = ab1[h];
    for (int k = 0; k < Hh; k++)
        acc += g_pool[b * Hh + k] * inv * A1[(Hh + k) * Hh + h] + ms[k] * A1[(2 * Hh + k) * Hh + h];
    g_bias1[b * Hh + h] = acc;
}

__global__ void k_final(const int* __restrict__ cand, const int* __restrict__ action,
                        const float* __restrict__ C1, const float* __restrict__ cb1,
                        const float* __restrict__ C2, const float* __restrict__ cb2,
                        float* __restrict__ out)
{
    int b = blockIdx.x, tid = threadIdx.x;
    __shared__ float sv[Nn];
    __shared__ float red[256];
    const float* sc = g_scores + b * Nn;
    const int* cd = cand + b * Nn;
    float mx = -3.4e38f;
    for (int i = tid; i < Nn; i += 256) mx = fmaxf(mx, sc[i]);
    red[tid] = mx; __syncthreads();
    for (int s = 128; s > 0; s >>= 1) { if (tid < s) red[tid] = fmaxf(red[tid], red[tid + s]); __syncthreads(); }
    float smax = red[0]; __syncthreads();
    float sum = 0.f;
    for (int i = tid; i < Nn; i += 256) { float e = expf(sc[i] - smax); sv[i] = e; sum += e; }
    red[tid] = sum; __syncthreads();
    for (int s = 128; s > 0; s >>= 1) { if (tid < s) red[tid] += red[tid + s]; __syncthreads(); }
    float tot = red[0]; __syncthreads();
    float m2 = -3.4e38f;
    for (int i = tid; i < Nn; i += 256) {
        float z = cd[i] ? (sv[i] / tot) : -1e9f;
        sv[i] = z; m2 = fmaxf(m2, z);
    }
    red[tid] = m2; __syncthreads();
    for (int s = 128; s > 0; s >>= 1) { if (tid < s) red[tid] = fmaxf(red[tid], red[tid + s]); __syncthreads(); }
    m2 = red[0]; __syncthreads();
    float se = 0.f;
    for (int i = tid; i < Nn; i += 256) se += expf(sv[i] - m2);
    red[tid] = se; __syncthreads();
    for (int s = 128; s > 0; s >>= 1) { if (tid < s) red[tid] += red[tid + s]; __syncthreads(); }
    float lse = logf(red[0]); __syncthreads();
    float ent = 0.f;
    for (int i = tid; i < Nn; i += 256) { float lp = sv[i] - m2 - lse; float p = expf(lp); ent -= p * lp; }
    red[tid] = ent; __syncthreads();
    for (int s = 128; s > 0; s >>= 1) { if (tid < s) red[tid] += red[tid + s]; __syncthreads(); }
    float entropy = red[0];
    if (tid == 0) {
        int a = action[b];
        out[b]      = (float)a;
        out[16 + b] = sv[a] - m2 - lse;
        out[32 + b] = entropy;
    }
    if (tid < 32) {
        const float inv = 1.f / 2048.f;
        float acc = cb1[tid];
        for (int h = 0; h < Hh; h++) acc += g_pool[b * Hh + h] * inv * C1[h * 32 + tid];
        float r = fmaxf(acc, 0.f) * C2[tid];
#pragma unroll
        for (int o = 16; o > 0; o >>= 1) r += __shfl_down_sync(0xffffffff, r, o);
        if (tid == 0) out[48 + b] = r + cb2[0];
    }
}

// ---------------- launch ----------------
extern "C" void kernel_launch(void* const* d_in, const int* in_sizes, int n_in,
                              void* d_out, int out_size) {
    const float* features = (const float*)d_in[0];
    const int*   adj      = (const int*)d_in[1];
    const int*   cand     = (const int*)d_in[2];
    const int*   action   = (const int*)d_in[3];
    const float* W1  = (const float*)d_in[4];
    const float* b1  = (const float*)d_in[5];
    const float* W2  = (const float*)d_in[6];
    const float* b2  = (const float*)d_in[7];
    const float* W3  = (const float*)d_in[8];
    const float* b3  = (const float*)d_in[9];
    const float* ms  = (const float*)d_in[10];
    const float* A1  = (const float*)d_in[11];
    const float* ab1 = (const float*)d_in[12];
    const float* A2  = (const float*)d_in[13];
    const float* ab2 = (const float*)d_in[14];
    const float* A3  = (const float*)d_in[15];
    const float* ab3 = (const float*)d_in[16];
    const float* C1  = (const float*)d_in[17];
    const float* cb1 = (const float*)d_in[18];
    const float* C2  = (const float*)d_in[19];
    const float* cb2 = (const float*)d_in[20];
    float* out = (float*)d_out;

    void *pAh, *pdeg, *pdis, *pXs, *ph, *pw16, *pbias1, *ppool, *pscores;
    cudaGetSymbolAddress(&pAh,  g_Ah);
    cudaGetSymbolAddress(&pdeg, g_deg);
    cudaGetSymbolAddress(&pdis, g_dis);
    cudaGetSymbolAddress(&pXs,  g_Xs);
    cudaGetSymbolAddress(&ph,   g_h);
    cudaGetSymbolAddress(&pw16, g_w16);
    cudaGetSymbolAddress(&pbias1, g_bias1);
    cudaGetSymbolAddress(&ppool, g_pool);
    cudaGetSymbolAddress(&pscores, g_scores);

    __half* Ah   = (__half*)pAh;
    __half* Xs   = (__half*)pXs;
    __half* Hbuf = (__half*)ph;
    __half* W16  = (__half*)pw16;
    float*  dis  = (float*)pdis;
    float*  bias1 = (float*)pbias1;
    float*  pool = (float*)ppool;
    float*  scores = (float*)pscores;

    const size_t HN = (size_t)Hh * Nn;
    const size_t NN = (size_t)Nn * Nn;

    cudaFuncSetAttribute(k_gemm, cudaFuncAttributeMaxDynamicSharedMemorySize, GEMM_SMEM);

    cudaMemsetAsync(pdeg, 0, Bb * Nn * sizeof(float));
    cudaMemsetAsync(ppool, 0, Bb * Hh * sizeof(float));
    k_deg_convert<<<dim3(32, Bb), 256>>>(adj);
    k_dis<<<(Bb * Nn) / 256, 256>>>();
    k_xs1<<<dim3(16, Bb), 256>>>(features, W1);

    dim3 gg(Nn / BN, Bb);
    // L1 agg  (launch #6 -> ncu profiles this)
    k_gemm<<<gg, NT, GEMM_SMEM>>>(Xs, HN, Nn, Ah, NN, Nn, Hbuf, HN, Nn,
                                  dis, b1, nullptr, 1, 0, nullptr, nullptr, nullptr, nullptr,
                                  nullptr, nullptr);
    // weight conversion (only needed before W2 proj)
    k_convw<<<(Hh * Hh) / 256, 256>>>(W2, W3, A1, A2);
    // W2 proj
    k_gemm<<<gg, NT, GEMM_SMEM>>>(W16, 0, Hh, Hbuf, HN, Nn, Xs, HN, Hh,
                                  dis, nullptr, nullptr, 0, 0, nullptr, nullptr, nullptr, nullptr,
                                  nullptr, nullptr);
    // L2 agg
    k_gemm<<<gg, NT, GEMM_SMEM>>>(Xs, HN, Nn, Ah, NN, Nn, Hbuf, HN, Nn,
                                  dis, b2, nullptr, 1, 0, nullptr, nullptr, nullptr, nullptr,
                                  nullptr, nullptr);
    // W3 proj
    k_gemm<<<gg, NT, GEMM_SMEM>>>(W16 + Hh * Hh, 0, Hh, Hbuf, HN, Nn, Xs, HN, Hh,
                                  dis, nullptr, nullptr, 0, 0, nullptr, nullptr, nullptr, nullptr,
                                  nullptr, nullptr);
    // L3 agg + fused pool
    k_gemm<<<gg, NT, GEMM_SMEM>>>(Xs, HN, Nn, Ah, NN, Nn, Hbuf, HN, Nn,
                                  dis, b3, nullptr, 1, 1, nullptr, nullptr, nullptr, nullptr,
                                  pool, nullptr);
    // actor bias from pool
    k_bias1<<<Bb, Hh>>>(A1, ab1, ms);
    // fused actor head: a1 = relu(A1lowT·h + bias1); a2 = relu(A2T·a1 + ab2); scores
    k_gemm<<<gg, NT, GEMM_SMEM>>>(W16 + 2 * Hh * Hh, 0, Hh, Hbuf, HN, Nn, Hbuf, HN, Hh,
                                  nullptr, nullptr, bias1, 1, 3, A3, ab3, ab2,
                                  W16 + 3 * Hh * Hh, nullptr, scores);
    k_final<<<Bb, 256>>>(cand, action, C1, cb1, C2, cb2, out);
}

// round 15
// speedup vs baseline: 1.0361x; 1.0361x over previous
#include <cuda_runtime.h>
#include <cuda_fp16.h>
#include <cstdint>

#define Bb 16
#define Nn 2048
#define Hh 128

// ---------------- scratch ----------------
__device__ __half g_Ah[(size_t)Bb * Nn * Nn];      // adj fp16 + self loops, [b][j][i]
__device__ float  g_deg[Bb * Nn];
__device__ float  g_dis[Bb * Nn];
__device__ __half g_Xs[(size_t)Bb * Hh * Nn];      // [b][h][j]
__device__ __half g_h [(size_t)Bb * Hh * Nn];
__device__ __half g_w16[4 * Hh * Hh];              // W2^T, W3^T, A1low^T, A2^T (row-major MxK)
__device__ float  g_pool[Bb * Hh];                 // raw sums (x2048)
__device__ float  g_bias1[Bb * Hh];
__device__ float  g_scores[Bb * Nn];

// ---------------- helpers ----------------
__device__ __forceinline__ uint32_t smem_u32(const void* p) {
    uint32_t a;
    asm("{ .reg .u64 t; cvta.to.shared.u64 t, %1; cvt.u32.u64 %0, t; }" : "=r"(a) : "l"(p));
    return a;
}
__device__ __forceinline__ void cp16(uint32_t s, const void* g) {
    asm volatile("cp.async.cg.shared.global [%0], [%1], 16;" :: "r"(s), "l"(g));
}
#define CP_COMMIT() asm volatile("cp.async.commit_group;" ::: "memory")
#define CP_WAIT(n)  asm volatile("cp.async.wait_group %0;" :: "n"(n) : "memory")

__device__ __forceinline__ void ldsm4(uint32_t* r, uint32_t addr) {
    asm volatile("ldmatrix.sync.aligned.m8n8.x4.shared.b16 {%0,%1,%2,%3}, [%4];"
                 : "=r"(r[0]), "=r"(r[1]), "=r"(r[2]), "=r"(r[3]) : "r"(addr));
}
__device__ __forceinline__ void ldsm4t(uint32_t* r, uint32_t addr) {
    asm volatile("ldmatrix.sync.aligned.m8n8.x4.trans.shared.b16 {%0,%1,%2,%3}, [%4];"
                 : "=r"(r[0]), "=r"(r[1]), "=r"(r[2]), "=r"(r[3]) : "r"(addr));
}
__device__ __forceinline__ void mma16816(float* c, const uint32_t* a, uint32_t b0, uint32_t b1) {
    asm volatile("mma.sync.aligned.m16n8k16.row.col.f32.f16.f16.f32 "
                 "{%0,%1,%2,%3}, {%4,%5,%6,%7}, {%8,%9}, {%0,%1,%2,%3};"
                 : "+f"(c[0]), "+f"(c[1]), "+f"(c[2]), "+f"(c[3])
                 : "r"(a[0]), "r"(a[1]), "r"(a[2]), "r"(a[3]), "r"(b0), "r"(b1));
}

// ---------------- degree + fp16 conversion (int4-vectorized) ----------------
__global__ void k_deg_convert(const int* __restrict__ adj) {
    int b  = blockIdx.y;
    int j0 = blockIdx.x * 64;
    int tid = threadIdx.x;
    int c0 = tid * 8;
    float sum[8];
#pragma unroll
    for (int s = 0; s < 8; s++) sum[s] = 0.f;
    const int*  base  = adj  + ((size_t)b * Nn + j0) * Nn;
    __half*     obase = g_Ah + ((size_t)b * Nn + j0) * Nn;
    for (int r = 0; r < 64; r++) {
        int j = j0 + r;
        const int4* row = (const int4*)(base + (size_t)r * Nn + c0);
        int4 v0 = row[0], v1 = row[1];
        float a[8];
        a[0] = (v0.x != 0 || j == c0 + 0) ? 1.f : 0.f;
        a[1] = (v0.y != 0 || j == c0 + 1) ? 1.f : 0.f;
        a[2] = (v0.z != 0 || j == c0 + 2) ? 1.f : 0.f;
        a[3] = (v0.w != 0 || j == c0 + 3) ? 1.f : 0.f;
        a[4] = (v1.x != 0 || j == c0 + 4) ? 1.f : 0.f;
        a[5] = (v1.y != 0 || j == c0 + 5) ? 1.f : 0.f;
        a[6] = (v1.z != 0 || j == c0 + 6) ? 1.f : 0.f;
        a[7] = (v1.w != 0 || j == c0 + 7) ? 1.f : 0.f;
        __half2 hb[4];
#pragma unroll
        for (int e = 0; e < 4; e++) hb[e] = __floats2half2_rn(a[2 * e], a[2 * e + 1]);
        *(uint4*)(obase + (size_t)r * Nn + c0) = *(const uint4*)hb;
#pragma unroll
        for (int e = 0; e < 8; e++) sum[e] += a[e];
    }
#pragma unroll
    for (int e = 0; e < 8; e++) atomicAdd(&g_deg[b * Nn + c0 + e], sum[e]);
}

__global__ void k_dis() {
    int i = blockIdx.x * 256 + threadIdx.x;
    g_dis[i] = rsqrtf(g_deg[i]);
}

__global__ void k_convw(const float* __restrict__ W2, const float* __restrict__ W3,
                        const float* __restrict__ A1, const float* __restrict__ A2) {
    int i = blockIdx.x * 256 + threadIdx.x;
    int r = i >> 7, c = i & 127;
    int t = c * 128 + r;
    g_w16[i]               = __float2half(W2[t]);
    g_w16[Hh * Hh + i]     = __float2half(W3[t]);
    g_w16[2 * Hh * Hh + i] = __float2half(A1[t]);
    g_w16[3 * Hh * Hh + i] = __float2half(A2[t]);
}

__global__ void k_xs1(const float* __restrict__ f, const float* __restrict__ W1) {
    int b = blockIdx.y, j0 = blockIdx.x * 128;
    int tid = threadIdx.x;
    __shared__ float sf0[128], sf1[128], sd[128], sw[256];
    if (tid < 128) {
        int j = j0 + tid;
        sf0[tid] = f[((size_t)b * Nn + j) * 2];
        sf1[tid] = f[((size_t)b * Nn + j) * 2 + 1];
        sd[tid]  = g_dis[b * Nn + j];
    }
    sw[tid] = W1[tid];
    __syncthreads();
#pragma unroll
    for (int t = 0; t < 32; t++) {
        int idx = t * 256 + tid;
        int h = idx >> 6, jp = (idx & 63) << 1;
        float v0 = sd[jp]     * (sf0[jp]     * sw[h] + sf1[jp]     * sw[128 + h]);
        float v1 = sd[jp + 1] * (sf0[jp + 1] * sw[h] + sf1[jp + 1] * sw[128 + h]);
        *(__half2*)(g_Xs + ((size_t)b * Hh + h) * Nn + j0 + jp) = __floats2half2_rn(v0, v1);
    }
}

// ---------------- mma.sync GEMM (templated on MODE) ----------------
// 4 warps (2x2), warp tile 64x64, BK=64, 3-stage cp.async, register double-buffered
// fragments, ONE barrier per k-iter, 2 CTAs/SM.
// MODE 0: store C fp16;  MODE 1: store C + pool atomics;
// MODE 3: fused actor head (a1 = relu(A·h + brbias); a2 = relu(Wproj·a1 + rb2); scores)
#define BM 128
#define BN 128
#define BK 64
#define NT 128
#define LDA_S 72
#define LDB_S 136
#define LDC_S 136
#define A_ST (BM * LDA_S)
#define B_ST (BK * LDB_S)
#define STAGE_H (A_ST + B_ST)
#define GEMM_SMEM (3 * STAGE_H * 2)   // 107520 B -> 2 CTAs/SM

#define LDSM_GROUP(AF, BF, as, bs, kk)                                   \
    do {                                                                 \
        _Pragma("unroll")                                                \
        for (int _x = 0; _x < 4; _x++)                                   \
            ldsm4(AF[_x], (as) + (_x * 16 * LDA_S + (kk)) * 2);          \
        _Pragma("unroll")                                                \
        for (int _y = 0; _y < 4; _y++)                                   \
            ldsm4t(BF[_y], (bs) + ((kk) * LDB_S + _y * 16) * 2);         \
    } while (0)

#define MMA_GROUP(AF, BF)                                                \
    do {                                                                 \
        _Pragma("unroll")                                                \
        for (int _x = 0; _x < 4; _x++)                                   \
            _Pragma("unroll")                                            \
            for (int _t = 0; _t < 8; _t++)                               \
                mma16816(c[_x][_t], AF[_x],                              \
                         BF[_t >> 1][(_t & 1) * 2],                      \
                         BF[_t >> 1][(_t & 1) * 2 + 1]);                 \
    } while (0)

template<int MODE>
__global__ void __launch_bounds__(NT, 2) k_gemm(
    const __half* __restrict__ gA, size_t sA, int lda,
    const __half* __restrict__ gB, size_t sB, int ldb,
    __half* __restrict__ gC, size_t sC, int K,
    const float* __restrict__ cscale, const float* __restrict__ rbias,
    const float* __restrict__ brbias, int doRelu,
    const float* __restrict__ pA3, const float* __restrict__ pab3,
    const float* __restrict__ rb2, const __half* __restrict__ Wproj,
    float* __restrict__ poolOut, float* __restrict__ scoresOut)
{
    extern __shared__ char smem[];
    uint32_t sb32 = smem_u32(smem);
    int tid = threadIdx.x, warp = tid >> 5, lane = tid & 31;
    int wm = warp >> 1, wn = warp & 1;            // 2 x 2 warps; warp tile 64 x 64
    int b = blockIdx.y, n0 = blockIdx.x * BN;
    const __half* A  = gA + (size_t)b * sA;
    const __half* Bp = gB + (size_t)b * sB;

    __shared__ float sb1[128];
    if (MODE == 3) sb1[tid] = brbias[b * Hh + tid];

    float c[4][8][4];
#pragma unroll
    for (int x = 0; x < 4; x++)
#pragma unroll
        for (int t = 0; t < 8; t++)
#pragma unroll
            for (int e = 0; e < 4; e++) c[x][t][e] = 0.f;

    auto load_stage = [&](int st, int k0) {
        uint32_t as = sb32 + st * STAGE_H * 2;
        uint32_t bs = as + A_ST * 2;
#pragma unroll
        for (int t = 0; t < 8; t++) {
            int cc = tid + t * NT;
            int ar = cc >> 3, ak = (cc & 7) << 3;
            cp16(as + (ar * LDA_S + ak) * 2, A + (size_t)ar * lda + k0 + ak);
        }
#pragma unroll
        for (int t = 0; t < 8; t++) {
            int cc = tid + t * NT;
            int br = cc >> 4, bn = (cc & 15) << 3;
            cp16(bs + (br * LDB_S + bn) * 2, Bp + (size_t)(k0 + br) * ldb + n0 + bn);
        }
    };

    uint32_t a_off = ((wm * 64 + (lane & 15)) * LDA_S + ((lane >> 4) << 3)) * 2;
    uint32_t b_off = ((lane & 15) * LDB_S + wn * 64 + ((lane >> 4) << 3)) * 2;

    uint32_t af0[4][4], bf0[4][4], af1[4][4], bf1[4][4];

    int KI = K >> 6;
    if (MODE == 3) {
        // preload Wproj (A2^T, 128x128 row-major) into stage-2 A region
        uint32_t ws = sb32 + 2 * STAGE_H * 2;
#pragma unroll
        for (int t = 0; t < 16; t++) {
            int cc = tid + t * NT;
            int ar = cc >> 4, ak = (cc & 15) << 3;
            cp16(ws + (ar * LDA_S + ak) * 2, Wproj + ar * Hh + ak);
        }
        CP_COMMIT();
    }
    load_stage(0, 0); CP_COMMIT();
    load_stage(1, BK); CP_COMMIT();
    CP_WAIT(1);
    __syncthreads();
    {
        uint32_t as = sb32 + a_off;
        uint32_t bs = sb32 + A_ST * 2 + b_off;
        LDSM_GROUP(af0, bf0, as, bs, 0);
    }

    for (int i = 0; i < KI; i++) {
        uint32_t as = sb32 + (i % 3) * STAGE_H * 2 + a_off;
        uint32_t bs = sb32 + (i % 3) * STAGE_H * 2 + A_ST * 2 + b_off;
        LDSM_GROUP(af1, bf1, as, bs, 16);
        MMA_GROUP(af0, bf0);
        LDSM_GROUP(af0, bf0, as, bs, 32);
        MMA_GROUP(af1, bf1);
        LDSM_GROUP(af1, bf1, as, bs, 48);
        MMA_GROUP(af0, bf0);
        if (MODE != 3 && i + 2 < KI) {
            load_stage((i + 2) % 3, (i + 2) * BK);
            CP_COMMIT();
            CP_WAIT(1);
        } else if (i < KI - 1) {
            CP_WAIT(0);
        }
        if (i < KI - 1) {
            __syncthreads();
            uint32_t as2 = sb32 + ((i + 1) % 3) * STAGE_H * 2 + a_off;
            uint32_t bs2 = sb32 + ((i + 1) % 3) * STAGE_H * 2 + A_ST * 2 + b_off;
            LDSM_GROUP(af0, bf0, as2, bs2, 0);
        }
        MMA_GROUP(af1, bf1);
    }
    __syncthreads();

    if (MODE == 3) {
        // a1 = relu(c + bias1) -> fp16 tile in slot0 (rows = feature, cols = node)
        __half* Hs = (__half*)smem;
        {
            int r = lane >> 2, cq = (lane & 3) * 2;
#pragma unroll
            for (int x = 0; x < 4; x++) {
                int m0 = wm * 64 + x * 16 + r;
                float bb0 = sb1[m0], bb1 = sb1[m0 + 8];
#pragma unroll
                for (int t = 0; t < 8; t++) {
                    int nb = wn * 64 + t * 8 + cq;
                    *(__half2*)(Hs + m0 * LDB_S + nb) =
                        __floats2half2_rn(fmaxf(c[x][t][0] + bb0, 0.f), fmaxf(c[x][t][1] + bb0, 0.f));
                    *(__half2*)(Hs + (m0 + 8) * LDB_S + nb) =
                        __floats2half2_rn(fmaxf(c[x][t][2] + bb1, 0.f), fmaxf(c[x][t][3] + bb1, 0.f));
                }
            }
        }
        __syncthreads();
        // second GEMM: a2 = A2^T (slot2 A region) * a1 (slot0), K=128
#pragma unroll
        for (int x = 0; x < 4; x++)
#pragma unroll
            for (int t = 0; t < 8; t++)
#pragma unroll
                for (int e = 0; e < 4; e++) c[x][t][e] = 0.f;
        uint32_t as2 = sb32 + 2 * STAGE_H * 2 + a_off;
        uint32_t bs2 = sb32 + b_off;
        LDSM_GROUP(af0, bf0, as2, bs2, 0);
#pragma unroll
        for (int kk = 0; kk < 128; kk += 32) {
            LDSM_GROUP(af1, bf1, as2, bs2, kk + 16);
            MMA_GROUP(af0, bf0);
            if (kk + 32 < 128) LDSM_GROUP(af0, bf0, as2, bs2, kk + 32);
            MMA_GROUP(af1, bf1);
        }
        __syncthreads();
    }

    // stage accumulators to fp32 smem
    float* Cs = (float*)smem;
    {
        int r = lane >> 2, cq = (lane & 3) * 2;
#pragma unroll
        for (int x = 0; x < 4; x++)
#pragma unroll
            for (int t = 0; t < 8; t++) {
                int base = (wm * 64 + x * 16 + r) * LDC_S + wn * 64 + t * 8 + cq;
                Cs[base]     = c[x][t][0];
                Cs[base + 1] = c[x][t][1];
                Cs[base + 8 * LDC_S]     = c[x][t][2];
                Cs[base + 8 * LDC_S + 1] = c[x][t][3];
            }
    }
    __syncthreads();

    const float* cs = cscale ? cscale + (size_t)b * Nn + n0 : nullptr;

    if (MODE == 3) {
        __shared__ float sA3[128], sb2[128];
        sA3[tid] = pA3[tid]; sb2[tid] = rb2[tid];
        __syncthreads();
        int n = tid;
        float accv = 0.f;
#pragma unroll 4
        for (int m = 0; m < 128; m++) {
            float v = fmaxf(Cs[m * LDC_S + n] + sb2[m], 0.f);
            accv += v * sA3[m];
        }
        scoresOut[(size_t)b * Nn + n0 + n] = 10.f * (accv + pab3[0]);
        return;
    }

    const float* bbp = brbias ? brbias + b * Hh : nullptr;
#pragma unroll
    for (int t = 0; t < 16; t++) {
        int cc = tid + t * NT;
        int m = cc >> 4, nc = (cc & 15) << 3;
        float rbv = 0.f;
        if (rbias) rbv += rbias[m];
        if (bbp)   rbv += bbp[m];
        __half2 hb[4];
#pragma unroll
        for (int e = 0; e < 8; e += 2) {
            float v0 = Cs[m * LDC_S + nc + e];
            float v1 = Cs[m * LDC_S + nc + e + 1];
            if (cs) { v0 *= cs[nc + e]; v1 *= cs[nc + e + 1]; }
            v0 += rbv; v1 += rbv;
            if (doRelu) { v0 = fmaxf(v0, 0.f); v1 = fmaxf(v1, 0.f); }
            hb[e >> 1] = __floats2half2_rn(v0, v1);
        }
        *(uint4*)(gC + (size_t)b * sC + (size_t)m * Nn + n0 + nc) = *(const uint4*)hb;
    }
    if (MODE == 1) {
        int m = tid;
        float rbv = rbias ? rbias[m] : 0.f;
        float part = 0.f;
#pragma unroll 4
        for (int n = 0; n < 128; n++) {
            float v = Cs[m * LDC_S + n];
            if (cs) v *= cs[n];
            part += fmaxf(v + rbv, 0.f);
        }
        atomicAdd(&poolOut[b * Hh + m], part);
    }
}

// ---------------- bias1, final ----------------
__global__ void k_bias1(const float* __restrict__ A1, const float* __restrict__ ab1,
                        const float* __restrict__ ms) {
    int b = blockIdx.x, h = threadIdx.x;
    const float inv = 1.f / 2048.f;
    float acc = ab1[h];
    for (int k = 0; k < Hh; k++)
        acc += g_pool[b * Hh + k] * inv * A1[(Hh + k) * Hh + h] + ms[k] * A1[(2 * Hh + k) * Hh + h];
    g_bias1[b * Hh + h] = acc;
}

__global__ void k_final(const int* __restrict__ cand, const int* __restrict__ action,
                        const float* __restrict__ C1, const float* __restrict__ cb1,
                        const float* __restrict__ C2, const float* __restrict__ cb2,
                        float* __restrict__ out)
{
    int b = blockIdx.x, tid = threadIdx.x;
    __shared__ float sv[Nn];
    __shared__ float red[256];
    const float* sc = g_scores + b * Nn;
    const int* cd = cand + b * Nn;
    float mx = -3.4e38f;
    for (int i = tid; i < Nn; i += 256) mx = fmaxf(mx, sc[i]);
    red[tid] = mx; __syncthreads();
    for (int s = 128; s > 0; s >>= 1) { if (tid < s) red[tid] = fmaxf(red[tid], red[tid + s]); __syncthreads(); }
    float smax = red[0]; __syncthreads();
    float sum = 0.f;
    for (int i = tid; i < Nn; i += 256) { float e = expf(sc[i] - smax); sv[i] = e; sum += e; }
    red[tid] = sum; __syncthreads();
    for (int s = 128; s > 0; s >>= 1) { if (tid < s) red[tid] += red[tid + s]; __syncthreads(); }
    float tot = red[0]; __syncthreads();
    float m2 = -3.4e38f;
    for (int i = tid; i < Nn; i += 256) {
        float z = cd[i] ? (sv[i] / tot) : -1e9f;
        sv[i] = z; m2 = fmaxf(m2, z);
    }
    red[tid] = m2; __syncthreads();
    for (int s = 128; s > 0; s >>= 1) { if (tid < s) red[tid] = fmaxf(red[tid], red[tid + s]); __syncthreads(); }
    m2 = red[0]; __syncthreads();
    float se = 0.f;
    for (int i = tid; i < Nn; i += 256) se += expf(sv[i] - m2);
    red[tid] = se; __syncthreads();
    for (int s = 128; s > 0; s >>= 1) { if (tid < s) red[tid] += red[tid + s]; __syncthreads(); }
    float lse = logf(red[0]); __syncthreads();
    float ent = 0.f;
    for (int i = tid; i < Nn; i += 256) { float lp = sv[i] - m2 - lse; float p = expf(lp); ent -= p * lp; }
    red[tid] = ent; __syncthreads();
    for (int s = 128; s > 0; s >>= 1) { if (tid < s) red[tid] += red[tid + s]; __syncthreads(); }
    float entropy = red[0];
    if (tid == 0) {
        int a = action[b];
        out[b]      = (float)a;
        out[16 + b] = sv[a] - m2 - lse;
        out[32 + b] = entropy;
    }
    if (tid < 32) {
        const float inv = 1.f / 2048.f;
        float acc = cb1[tid];
        for (int h = 0; h < Hh; h++) acc += g_pool[b * Hh + h] * inv * C1[h * 32 + tid];
        float r = fmaxf(acc, 0.f) * C2[tid];
#pragma unroll
        for (int o = 16; o > 0; o >>= 1) r += __shfl_down_sync(0xffffffff, r, o);
        if (tid == 0) out[48 + b] = r + cb2[0];
    }
}

// ---------------- launch ----------------
extern "C" void kernel_launch(void* const* d_in, const int* in_sizes, int n_in,
                              void* d_out, int out_size) {
    const float* features = (const float*)d_in[0];
    const int*   adj      = (const int*)d_in[1];
    const int*   cand     = (const int*)d_in[2];
    const int*   action   = (const int*)d_in[3];
    const float* W1  = (const float*)d_in[4];
    const float* b1  = (const float*)d_in[5];
    const float* W2  = (const float*)d_in[6];
    const float* b2  = (const float*)d_in[7];
    const float* W3  = (const float*)d_in[8];
    const float* b3  = (const float*)d_in[9];
    const float* ms  = (const float*)d_in[10];
    const float* A1  = (const float*)d_in[11];
    const float* ab1 = (const float*)d_in[12];
    const float* A2  = (const float*)d_in[13];
    const float* ab2 = (const float*)d_in[14];
    const float* A3  = (const float*)d_in[15];
    const float* ab3 = (const float*)d_in[16];
    const float* C1  = (const float*)d_in[17];
    const float* cb1 = (const float*)d_in[18];
    const float* C2  = (const float*)d_in[19];
    const float* cb2 = (const float*)d_in[20];
    float* out = (float*)d_out;

    void *pAh, *pdeg, *pdis, *pXs, *ph, *pw16, *pbias1, *ppool, *pscores;
    cudaGetSymbolAddress(&pAh,  g_Ah);
    cudaGetSymbolAddress(&pdeg, g_deg);
    cudaGetSymbolAddress(&pdis, g_dis);
    cudaGetSymbolAddress(&pXs,  g_Xs);
    cudaGetSymbolAddress(&ph,   g_h);
    cudaGetSymbolAddress(&pw16, g_w16);
    cudaGetSymbolAddress(&pbias1, g_bias1);
    cudaGetSymbolAddress(&ppool, g_pool);
    cudaGetSymbolAddress(&pscores, g_scores);

    __half* Ah   = (__half*)pAh;
    __half* Xs   = (__half*)pXs;
    __half* Hbuf = (__half*)ph;
    __half* W16  = (__half*)pw16;
    float*  dis  = (float*)pdis;
    float*  bias1 = (float*)pbias1;
    float*  pool = (float*)ppool;
    float*  scores = (float*)pscores;

    const size_t HN = (size_t)Hh * Nn;
    const size_t NN = (size_t)Nn * Nn;

    cudaFuncSetAttribute(k_gemm<0>, cudaFuncAttributeMaxDynamicSharedMemorySize, GEMM_SMEM);
    cudaFuncSetAttribute(k_gemm<1>, cudaFuncAttributeMaxDynamicSharedMemorySize, GEMM_SMEM);
    cudaFuncSetAttribute(k_gemm<3>, cudaFuncAttributeMaxDynamicSharedMemorySize, GEMM_SMEM);

    cudaMemsetAsync(pdeg, 0, Bb * Nn * sizeof(float));
    cudaMemsetAsync(ppool, 0, Bb * Hh * sizeof(float));
    k_deg_convert<<<dim3(32, Bb), 256>>>(adj);
    k_dis<<<(Bb * Nn) / 256, 256>>>();
    k_xs1<<<dim3(16, Bb), 256>>>(features, W1);

    dim3 gg(Nn / BN, Bb);
    // L1 agg  (launch #6 -> ncu profiles this)
    k_gemm<0><<<gg, NT, GEMM_SMEM>>>(Xs, HN, Nn, Ah, NN, Nn, Hbuf, HN, Nn,
                                     dis, b1, nullptr, 1, nullptr, nullptr, nullptr, nullptr,
                                     nullptr, nullptr);
    // weight conversion (only needed before W2 proj)
    k_convw<<<(Hh * Hh) / 256, 256>>>(W2, W3, A1, A2);
    // W2 proj
    k_gemm<0><<<gg, NT, GEMM_SMEM>>>(W16, 0, Hh, Hbuf, HN, Nn, Xs, HN, Hh,
                                     dis, nullptr, nullptr, 0, nullptr, nullptr, nullptr, nullptr,
                                     nullptr, nullptr);
    // L2 agg
    k_gemm<0><<<gg, NT, GEMM_SMEM>>>(Xs, HN, Nn, Ah, NN, Nn, Hbuf, HN, Nn,
                                     dis, b2, nullptr, 1, nullptr, nullptr, nullptr, nullptr,
                                     nullptr, nullptr);
    // W3 proj
    k_gemm<0><<<gg, NT, GEMM_SMEM>>>(W16 + Hh * Hh, 0, Hh, Hbuf, HN, Nn, Xs, HN, Hh,
                                     dis, nullptr, nullptr, 0, nullptr, nullptr, nullptr, nullptr,
                                     nullptr, nullptr);
    // L3 agg + fused pool
    k_gemm<1><<<gg, NT, GEMM_SMEM>>>(Xs, HN, Nn, Ah, NN, Nn, Hbuf, HN, Nn,
                                     dis, b3, nullptr, 1, nullptr, nullptr, nullptr, nullptr,
                                     pool, nullptr);
    // actor bias from pool
    k_bias1<<<Bb, Hh>>>(A1, ab1, ms);
    // fused actor head: a1 = relu(A1lowT·h + bias1); a2 = relu(A2T·a1 + ab2); scores
    k_gemm<3><<<gg, NT, GEMM_SMEM>>>(W16 + 2 * Hh * Hh, 0, Hh, Hbuf, HN, Nn, Hbuf, HN, Hh,
                                     nullptr, nullptr, bias1, 1, A3, ab3, ab2,
                                     W16 + 3 * Hh * Hh, nullptr, scores);
    k_final<<<Bb, 256>>>(cand, action, C1, cb1, C2, cb2, out);
}